// round 5
// baseline (speedup 1.0000x reference)
#include <cuda_runtime.h>

// ---------------------------------------------------------------------------
// ECLoss: expected-calibration-style loss with three KDE evaluations per
// MC query point per bin. Hot loop = 4.65e9 Gaussian kernel evals, done as
// 2 FFMA + FADD + MUFU.EX2 + FADD per pair over shared-memory data tiles.
// ---------------------------------------------------------------------------

namespace {
constexpr int NTR    = 20000;
constexpr int NTE    = 10000;
constexpr int NBATCH = 1024;
constexpr int NQ     = 10000;
constexpr int NBINS  = 15;
constexpr int NCLS   = 10;
constexpr int THREADS = 256;
constexpr int QBLOCKS = (NQ + THREADS - 1) / THREADS;  // 40
constexpr int TILE    = 1024;

constexpr double BW_D   = 0.3;
constexpr double PI_D   = 3.14159265358979323846;
constexpr double L2E_D  = 1.4426950408889634073599246810019;
constexpr double KDEN_D = 2.0 * PI_D * BW_D * BW_D;          // 0.565486677646...

constexpr float C1 = (float)(L2E_D / (BW_D * BW_D));         // dot coefficient
constexpr float C2 = (float)(L2E_D / (2.0 * BW_D * BW_D));   // norm coefficient
constexpr float KDEN_F   = (float)KDEN_D;
constexpr float DEN_TR   = (float)((double)NTR * KDEN_D);
constexpr float DEN_TE   = (float)((double)NTE * KDEN_D);
constexpr float L2E_F    = (float)L2E_D;
constexpr float BIN_STEP = 1.0f / 15.0f;   // fl(1/15), matches linspace step
}

// Transformed data: (ax, ay, az, pad). Weighted (batch) points with weight 0
// get az = -1e30 so exp2 -> 0.
__device__ float4 g_tr[NTR];
__device__ float4 g_te[NTE];
__device__ float4 g_bw[NBATCH];
__device__ int    g_hist_tr[NBINS];
__device__ int    g_hist_te[NBINS];
__device__ int    g_cnt;
__device__ float  g_partial[NBINS * QBLOCKS];

__device__ __forceinline__ float ex2(float x) {
    float r;
    asm("ex2.approx.ftz.f32 %0, %1;" : "=f"(r) : "f"(x));
    return r;
}

__device__ __forceinline__ float bin_lo(int k) {
    return (float)k * BIN_STEP;
}
__device__ __forceinline__ float bin_hi(int k) {
    return (k == NBINS - 1) ? 1.0f : (float)(k + 1) * BIN_STEP;  // linspace endpoint
}

// --------------------------- init ------------------------------------------
__global__ void ec_init_kernel() {
    int t = threadIdx.x;
    if (t < NBINS) { g_hist_tr[t] = 0; g_hist_te[t] = 0; }
    if (t == 0)    g_cnt = 0;
}

// --------------------------- prep ------------------------------------------
// Transforms all data points and builds prob histograms + correct count.
__global__ void ec_prep_kernel(const float* __restrict__ train_x,
                               const float* __restrict__ test_x,
                               const float* __restrict__ batch_x,
                               const int*   __restrict__ by,
                               const int*   __restrict__ bp,
                               const float* __restrict__ train_probs,
                               const float* __restrict__ test_probs) {
    int i = blockIdx.x * blockDim.x + threadIdx.x;
    if (i < NTR) {
        float x = train_x[2 * i], y = train_x[2 * i + 1];
        g_tr[i] = make_float4(x * C1, y * C1, -(x * x + y * y) * C2, 0.0f);
        float p = train_probs[i];
        #pragma unroll
        for (int k = 0; k < NBINS; k++) {
            if (p > bin_lo(k) && p <= bin_hi(k)) { atomicAdd(&g_hist_tr[k], 1); break; }
        }
    } else if (i < NTR + NTE) {
        int j = i - NTR;
        float x = test_x[2 * j], y = test_x[2 * j + 1];
        g_te[j] = make_float4(x * C1, y * C1, -(x * x + y * y) * C2, 0.0f);
        float p = test_probs[j];
        #pragma unroll
        for (int k = 0; k < NBINS; k++) {
            if (p > bin_lo(k) && p <= bin_hi(k)) { atomicAdd(&g_hist_te[k], 1); break; }
        }
    } else if (i < NTR + NTE + NBATCH) {
        int j = i - NTR - NTE;
        float x = batch_x[2 * j], y = batch_x[2 * j + 1];
        bool c = (by[j] == bp[j]);
        if (c) atomicAdd(&g_cnt, 1);
        g_bw[j] = make_float4(x * C1, y * C1,
                              c ? -(x * x + y * y) * C2 : -1e30f, 0.0f);
    }
}

// --------------------------- main ------------------------------------------
__device__ __forceinline__ float kde_sum(const float4* __restrict__ data, int n,
                                         float qx, float qy, float qc,
                                         float4* tile) {
    float a0 = 0.f, a1 = 0.f, a2 = 0.f, a3 = 0.f;
    for (int base = 0; base < n; base += TILE) {
        int m = min(TILE, n - base);
        __syncthreads();
        for (int j = threadIdx.x; j < m; j += THREADS) tile[j] = data[base + j];
        __syncthreads();
        int j = 0;
        for (; j + 4 <= m; j += 4) {
            float4 d0 = tile[j + 0];
            float4 d1 = tile[j + 1];
            float4 d2 = tile[j + 2];
            float4 d3 = tile[j + 3];
            a0 += ex2(fmaf(d0.x, qx, fmaf(d0.y, qy, d0.z) + qc));
            a1 += ex2(fmaf(d1.x, qx, fmaf(d1.y, qy, d1.z) + qc));
            a2 += ex2(fmaf(d2.x, qx, fmaf(d2.y, qy, d2.z) + qc));
            a3 += ex2(fmaf(d3.x, qx, fmaf(d3.y, qy, d3.z) + qc));
        }
        for (; j < m; j++) {
            float4 d = tile[j];
            a0 += ex2(fmaf(d.x, qx, fmaf(d.y, qy, d.z) + qc));
        }
    }
    return (a0 + a1) + (a2 + a3);
}

__global__ void __launch_bounds__(THREADS)
ec_main_kernel(const float* __restrict__ mc,
               const float* __restrict__ W,
               const float* __restrict__ b) {
    __shared__ float4 tile[TILE];
    __shared__ float  red[THREADS];

    int bin = blockIdx.y;
    int q   = blockIdx.x * THREADS + threadIdx.x;

    float qx = 0.0f, qy = 0.0f;
    if (q < NQ) {
        const float* qp = mc + ((size_t)bin * NQ + (size_t)q) * 2;
        qx = qp[0];
        qy = qp[1];
    }
    float qc = -(qx * qx + qy * qy) * C2;

    float s_tr = kde_sum(g_tr, NTR,    qx, qy, qc, tile);
    float s_te = kde_sum(g_te, NTE,    qx, qy, qc, tile);
    float s_w  = kde_sum(g_bw, NBATCH, qx, qy, qc, tile);

    // ---- per-query epilogue ----
    float cnt   = (float)g_cnt;
    float maxc  = fmaxf(cnt, 1.0f);
    float p_y   = cnt * (1.0f / 1024.0f);        // exact (power of 2)
    float kde_tr = s_tr / DEN_TR;
    float kde_te = s_te / DEN_TE;
    float kde_w  = s_w  / (maxc * KDEN_F);

    float tr_rate = (float)g_hist_tr[bin] / 20000.0f;
    float te_rate = (float)g_hist_te[bin] / 10000.0f;

    // hat_s = max softmax(x@W + b) = 1 / sum exp(l - lmax)
    float l[NCLS];
    float lmax = -1e30f;
    #pragma unroll
    for (int c = 0; c < NCLS; c++) {
        l[c] = fmaf(qx, W[c], fmaf(qy, W[NCLS + c], b[c]));
        lmax = fmaxf(lmax, l[c]);
    }
    float se = 0.0f;
    #pragma unroll
    for (int c = 0; c < NCLS; c++) se += ex2((l[c] - lmax) * L2E_F);
    float hat_s = 1.0f / se;

    float lo = bin_lo(bin), hi = bin_hi(bin);
    float idx = (hat_s >= lo && hat_s <= hi) ? 1.0f : 0.0f;

    float d_t = (te_rate > 0.0f) ? kde_te / te_rate : 0.0f;
    float d_s = (tr_rate > 0.0f) ? kde_tr / tr_rate : 0.0f;

    float p_hs = kde_w * p_y / (kde_tr + 1e-8f);
    p_hs = fminf(fmaxf(p_hs, 0.0f), 1.0f);

    float contrib = (q < NQ) ? p_hs * (d_t - d_s) * idx : 0.0f;

    // ---- deterministic block reduction ----
    red[threadIdx.x] = contrib;
    __syncthreads();
    #pragma unroll
    for (int s = THREADS / 2; s > 0; s >>= 1) {
        if (threadIdx.x < s) red[threadIdx.x] += red[threadIdx.x + s];
        __syncthreads();
    }
    if (threadIdx.x == 0)
        g_partial[bin * QBLOCKS + blockIdx.x] = red[0];
}

// --------------------------- final -----------------------------------------
__global__ void ec_final_kernel(float* __restrict__ out) {
    __shared__ float binv[NBINS];
    int t = threadIdx.x;
    if (t < NBINS) {
        float s = 0.0f;
        for (int b2 = 0; b2 < QBLOCKS; b2++) s += g_partial[t * QBLOCKS + b2];
        float integral = (s / (float)NQ) * 100.0f;   // mean * VOLUME
        float te_rate  = (float)g_hist_te[t] / 10000.0f;
        binv[t] = (te_rate > 0.0f) ? te_rate * fabsf(integral) : 0.0f;
    }
    __syncthreads();
    if (t == 0) {
        float ec = 0.0f;
        for (int k = 0; k < NBINS; k++) ec += binv[k];  // scan order 0..14
        out[0] = ec;
    }
}

// --------------------------- launch ----------------------------------------
extern "C" void kernel_launch(void* const* d_in, const int* in_sizes, int n_in,
                              void* d_out, int out_size) {
    const float* batch_x = (const float*)d_in[0];   // (1024, 2)
    const int*   by      = (const int*)  d_in[1];   // (1024,)
    const int*   bp      = (const int*)  d_in[2];   // (1024,)
    const float* trp     = (const float*)d_in[3];   // (20000,)
    const float* tep     = (const float*)d_in[4];   // (10000,)

    // Disambiguate dict order (train_x, test_x, W, b, mc) vs signature order
    // (W, b, train_x, test_x, mc) via element counts.
    const float *train_x, *test_x, *W, *b, *mc;
    if (in_sizes[5] == NTR * 2) {
        train_x = (const float*)d_in[5];
        test_x  = (const float*)d_in[6];
        W       = (const float*)d_in[7];
        b       = (const float*)d_in[8];
        mc      = (const float*)d_in[9];
    } else {
        W       = (const float*)d_in[5];
        b       = (const float*)d_in[6];
        train_x = (const float*)d_in[7];
        test_x  = (const float*)d_in[8];
        mc      = (const float*)d_in[9];
    }

    ec_init_kernel<<<1, 32>>>();

    int total = NTR + NTE + NBATCH;
    ec_prep_kernel<<<(total + 255) / 256, 256>>>(train_x, test_x, batch_x,
                                                 by, bp, trp, tep);

    dim3 grid(QBLOCKS, NBINS);
    ec_main_kernel<<<grid, THREADS>>>(mc, W, b);

    ec_final_kernel<<<1, 32>>>((float*)d_out);
}